// round 2
// baseline (speedup 1.0000x reference)
#include <cuda_runtime.h>
#include <cuda_bf16.h>
#include <cstdint>

// ============================================================================
// out[8192,4096] = x[8192,4096] @ ternary(W)^T[4096,4096] + bias
// Engine: Ampere-style cp.async + ldmatrix + mma.sync bf16 (baseline sm_100 PTX,
// no 'a'-gated instructions). x split into bf16 hi+lo for fp32-grade accuracy.
// ============================================================================
#define M_TOTAL 8192
#define N_TOTAL 4096
#define K_TOTAL 4096

__device__ __nv_bfloat16 g_xhi[(size_t)M_TOTAL * K_TOTAL];
__device__ __nv_bfloat16 g_xlo[(size_t)M_TOTAL * K_TOTAL];
__device__ __nv_bfloat16 g_wq [(size_t)N_TOTAL * K_TOTAL];

// ============================================================================
// Kernel 1: ternary-quantize W rows -> bf16 {-1,0,1}; thresh = 0.7*mean(|row|)
// ============================================================================
__global__ void __launch_bounds__(256) quant_w_kernel(const float* __restrict__ w,
                                                      uint2* __restrict__ wq) {
    const int row = blockIdx.x;
    const float4* wr = reinterpret_cast<const float4*>(w + (size_t)row * K_TOTAL);
    float s = 0.f;
#pragma unroll
    for (int i = 0; i < 4; ++i) {
        float4 v = wr[threadIdx.x + i * 256];
        s += fabsf(v.x) + fabsf(v.y) + fabsf(v.z) + fabsf(v.w);
    }
#pragma unroll
    for (int o = 16; o; o >>= 1) s += __shfl_xor_sync(0xffffffffu, s, o);
    __shared__ float warp_sums[8];
    if ((threadIdx.x & 31) == 0) warp_sums[threadIdx.x >> 5] = s;
    __syncthreads();
    float tot = 0.f;
#pragma unroll
    for (int i = 0; i < 8; ++i) tot += warp_sums[i];
    const float t = 0.7f * (tot * (1.0f / (float)K_TOTAL));

    uint2* wo = wq + (size_t)row * (K_TOTAL / 4);
#pragma unroll
    for (int i = 0; i < 4; ++i) {
        const int idx = threadIdx.x + i * 256;
        float4 v = wr[idx];
        float q0 = v.x > t ? 1.f : (v.x < -t ? -1.f : 0.f);
        float q1 = v.y > t ? 1.f : (v.y < -t ? -1.f : 0.f);
        float q2 = v.z > t ? 1.f : (v.z < -t ? -1.f : 0.f);
        float q3 = v.w > t ? 1.f : (v.w < -t ? -1.f : 0.f);
        __nv_bfloat162 p0 = __floats2bfloat162_rn(q0, q1);
        __nv_bfloat162 p1 = __floats2bfloat162_rn(q2, q3);
        uint2 u;
        u.x = *reinterpret_cast<uint32_t*>(&p0);
        u.y = *reinterpret_cast<uint32_t*>(&p1);
        wo[idx] = u;
    }
}

// ============================================================================
// Kernel 2: split x (fp32) -> x_hi (bf16) + x_lo (bf16 of exact residual)
// ============================================================================
__global__ void __launch_bounds__(256) conv_x_kernel(const float4* __restrict__ x4,
                                                     uint2* __restrict__ hi,
                                                     uint2* __restrict__ lo) {
    const int i = blockIdx.x * 256 + threadIdx.x;
    float4 v = x4[i];
    __nv_bfloat16 h0 = __float2bfloat16_rn(v.x);
    __nv_bfloat16 h1 = __float2bfloat16_rn(v.y);
    __nv_bfloat16 h2 = __float2bfloat16_rn(v.z);
    __nv_bfloat16 h3 = __float2bfloat16_rn(v.w);
    __nv_bfloat16 l0 = __float2bfloat16_rn(v.x - __bfloat162float(h0));
    __nv_bfloat16 l1 = __float2bfloat16_rn(v.y - __bfloat162float(h1));
    __nv_bfloat16 l2 = __float2bfloat16_rn(v.z - __bfloat162float(h2));
    __nv_bfloat16 l3 = __float2bfloat16_rn(v.w - __bfloat162float(h3));
    __nv_bfloat162 ph0 = __nv_bfloat162(h0, h1);
    __nv_bfloat162 ph1 = __nv_bfloat162(h2, h3);
    __nv_bfloat162 pl0 = __nv_bfloat162(l0, l1);
    __nv_bfloat162 pl1 = __nv_bfloat162(l2, l3);
    uint2 uh, ul;
    uh.x = *reinterpret_cast<uint32_t*>(&ph0);
    uh.y = *reinterpret_cast<uint32_t*>(&ph1);
    ul.x = *reinterpret_cast<uint32_t*>(&pl0);
    ul.y = *reinterpret_cast<uint32_t*>(&pl1);
    hi[i] = uh;
    lo[i] = ul;
}

// ============================================================================
// GEMM: 128x256 CTA tile, BK=64, 3-stage cp.async pipeline, 8 warps (2x4),
// warp tile 64x64, mma.sync m16n8k16 bf16. Two passes (hi, lo) share B frags.
// ============================================================================
constexpr int BM = 128, BN = 256, BK = 64, STAGES = 3;
constexpr int K_ITERS = K_TOTAL / BK;            // 64
constexpr int A_BYTES = BM * BK * 2;             // 16384
constexpr int B_BYTES = BN * BK * 2;             // 32768
constexpr int STAGE_BYTES = 2 * A_BYTES + B_BYTES;  // 65536
constexpr int SMEM_BYTES = STAGES * STAGE_BYTES;    // 196608

__device__ __forceinline__ void cp16(uint32_t s, const void* g) {
    asm volatile("cp.async.cg.shared.global [%0], [%1], 16;" :: "r"(s), "l"(g));
}
__device__ __forceinline__ void ldsm4(uint32_t* d, uint32_t a) {
    asm volatile("ldmatrix.sync.aligned.m8n8.x4.shared.b16 {%0,%1,%2,%3}, [%4];"
                 : "=r"(d[0]), "=r"(d[1]), "=r"(d[2]), "=r"(d[3]) : "r"(a));
}
__device__ __forceinline__ void mma16816(float* c, const uint32_t* a,
                                         uint32_t b0, uint32_t b1) {
    asm volatile(
        "mma.sync.aligned.m16n8k16.row.col.f32.bf16.bf16.f32 "
        "{%0,%1,%2,%3}, {%4,%5,%6,%7}, {%8,%9}, {%0,%1,%2,%3};"
        : "+f"(c[0]), "+f"(c[1]), "+f"(c[2]), "+f"(c[3])
        : "r"(a[0]), "r"(a[1]), "r"(a[2]), "r"(a[3]), "r"(b0), "r"(b1));
}

__global__ void __launch_bounds__(256, 1) ternary_gemm_kernel(
    const __nv_bfloat16* __restrict__ xhi,
    const __nv_bfloat16* __restrict__ xlo,
    const __nv_bfloat16* __restrict__ wq,
    const float* __restrict__ bias,
    float* __restrict__ out)
{
    extern __shared__ __align__(1024) char smem[];
    const uint32_t sb = (uint32_t)__cvta_generic_to_shared(smem);
    const int tid = threadIdx.x;
    const int wid = tid >> 5;
    const int lid = tid & 31;
    const int warp_m = wid & 1;       // 0..1 -> 64-row slab
    const int warp_n = wid >> 1;      // 0..3 -> 64-col slab
    const int m0 = blockIdx.y * BM;
    const int n0 = blockIdx.x * BN;

    // ---- stage loader: 16B chunks, XOR-8 swizzle on 128B rows ----
    auto load_stage = [&](int slot, int k0) {
        const uint32_t base = sb + slot * STAGE_BYTES;
#pragma unroll
        for (int i = 0; i < 4; ++i) {           // A hi: 128x64 = 1024 chunks
            int c = tid + i * 256, row = c >> 3, ch = c & 7;
            cp16(base + row * 128 + ((ch ^ (row & 7)) << 4),
                 xhi + (size_t)(m0 + row) * K_TOTAL + k0 + ch * 8);
        }
#pragma unroll
        for (int i = 0; i < 4; ++i) {           // A lo
            int c = tid + i * 256, row = c >> 3, ch = c & 7;
            cp16(base + A_BYTES + row * 128 + ((ch ^ (row & 7)) << 4),
                 xlo + (size_t)(m0 + row) * K_TOTAL + k0 + ch * 8);
        }
#pragma unroll
        for (int i = 0; i < 8; ++i) {           // B: 256x64 = 2048 chunks
            int c = tid + i * 256, row = c >> 3, ch = c & 7;
            cp16(base + 2 * A_BYTES + row * 128 + ((ch ^ (row & 7)) << 4),
                 wq + (size_t)(n0 + row) * K_TOTAL + k0 + ch * 8);
        }
    };

    float acc[4][8][4];
#pragma unroll
    for (int i = 0; i < 4; ++i)
#pragma unroll
        for (int j = 0; j < 8; ++j)
#pragma unroll
            for (int r = 0; r < 4; ++r) acc[i][j][r] = 0.f;

    // ---- prologue: fill STAGES-1 stages ----
#pragma unroll
    for (int s = 0; s < STAGES - 1; ++s) {
        load_stage(s, s * BK);
        asm volatile("cp.async.commit_group;" ::: "memory");
    }

    // lane-constant address pieces (swizzle phase = lid&7 for both A and B)
    const uint32_t sw   = lid & 7;
    const uint32_t aoff = (warp_m * 64 + (lid & 15)) * 128;
    const uint32_t acb  = (uint32_t)(lid >> 4);
    const uint32_t boff = 2 * A_BYTES +
                          (warp_n * 64 + ((lid >> 4) << 3) + (lid & 7)) * 128;
    const uint32_t bcb  = (lid >> 3) & 1;

    for (int it = 0; it < K_ITERS; ++it) {
        asm volatile("cp.async.wait_group %0;" :: "n"(STAGES - 2) : "memory");
        __syncthreads();
        const int nx = it + STAGES - 1;
        if (nx < K_ITERS) load_stage(nx % STAGES, nx * BK);
        asm volatile("cp.async.commit_group;" ::: "memory");

        const uint32_t st = sb + (it % STAGES) * STAGE_BYTES;
#pragma unroll
        for (int k16 = 0; k16 < 4; ++k16) {
            uint32_t b[4][4];
#pragma unroll
            for (int p = 0; p < 4; ++p)      // 2 n-tiles per ldmatrix.x4
                ldsm4(b[p], st + boff + p * 2048 + (((bcb + 2 * k16) ^ sw) << 4));
            uint32_t a[4][4];
#pragma unroll
            for (int mt = 0; mt < 4; ++mt)   // A hi frags
                ldsm4(a[mt], st + aoff + mt * 2048 + (((acb + 2 * k16) ^ sw) << 4));
#pragma unroll
            for (int mt = 0; mt < 4; ++mt)
#pragma unroll
                for (int nt = 0; nt < 8; ++nt)
                    mma16816(acc[mt][nt], a[mt],
                             b[nt >> 1][(nt & 1) * 2], b[nt >> 1][(nt & 1) * 2 + 1]);
#pragma unroll
            for (int mt = 0; mt < 4; ++mt)   // A lo frags (reuse regs, same B)
                ldsm4(a[mt], st + A_BYTES + aoff + mt * 2048 +
                             (((acb + 2 * k16) ^ sw) << 4));
#pragma unroll
            for (int mt = 0; mt < 4; ++mt)
#pragma unroll
                for (int nt = 0; nt < 8; ++nt)
                    mma16816(acc[mt][nt], a[mt],
                             b[nt >> 1][(nt & 1) * 2], b[nt >> 1][(nt & 1) * 2 + 1]);
        }
    }

    // ---- epilogue: bias add + float2 stores ----
    const int g = lid >> 2, t = lid & 3;
#pragma unroll
    for (int mt = 0; mt < 4; ++mt) {
        const int row = m0 + warp_m * 64 + mt * 16 + g;
        float* o0 = out + (size_t)row * N_TOTAL;
        float* o1 = out + (size_t)(row + 8) * N_TOTAL;
#pragma unroll
        for (int nt = 0; nt < 8; ++nt) {
            const int col = n0 + warp_n * 64 + nt * 8 + 2 * t;
            const float2 bv = *reinterpret_cast<const float2*>(bias + col);
            float2 v0 = {acc[mt][nt][0] + bv.x, acc[mt][nt][1] + bv.y};
            float2 v1 = {acc[mt][nt][2] + bv.x, acc[mt][nt][3] + bv.y};
            *reinterpret_cast<float2*>(o0 + col) = v0;
            *reinterpret_cast<float2*>(o1 + col) = v1;
        }
    }
}

// ============================================================================
// Host launcher
// ============================================================================
extern "C" void kernel_launch(void* const* d_in, const int* in_sizes, int n_in,
                              void* d_out, int out_size) {
    const float* x    = (const float*)d_in[0];
    const float* w    = (const float*)d_in[1];
    const float* bias = (const float*)d_in[2];
    float* out        = (float*)d_out;

    void *xhi, *xlo, *wq;
    cudaGetSymbolAddress(&xhi, g_xhi);
    cudaGetSymbolAddress(&xlo, g_xlo);
    cudaGetSymbolAddress(&wq,  g_wq);

    quant_w_kernel<<<N_TOTAL, 256>>>(w, (uint2*)wq);
    conv_x_kernel<<<(int)(((size_t)M_TOTAL * K_TOTAL) / (4 * 256)), 256>>>(
        (const float4*)x, (uint2*)xhi, (uint2*)xlo);

    static bool attr_set = false;
    if (!attr_set) {
        cudaFuncSetAttribute(ternary_gemm_kernel,
                             cudaFuncAttributeMaxDynamicSharedMemorySize, SMEM_BYTES);
        attr_set = true;
    }
    dim3 grid(N_TOTAL / BN, M_TOTAL / BM);
    ternary_gemm_kernel<<<grid, 256, SMEM_BYTES>>>(
        (const __nv_bfloat16*)xhi, (const __nv_bfloat16*)xlo,
        (const __nv_bfloat16*)wq, bias, out);
}

// round 3
// speedup vs baseline: 1.6860x; 1.6860x over previous
#include <cuda_runtime.h>
#include <cuda_fp16.h>
#include <cstdint>

// ============================================================================
// out[8192,4096] = x[8192,4096] @ ternary(W)^T[4096,4096] + bias
// Engine: cp.async + ldmatrix + mma.sync m16n8k16 fp16->fp32 (baseline sm_100).
// Single fp16 pass: ternary weights exact in fp16; x fp16 rounding gives
// ~2e-4 norm rel_err vs the 1e-3 gate.
// ============================================================================
#define M_TOTAL 8192
#define N_TOTAL 4096
#define K_TOTAL 4096

__device__ __half g_xh[(size_t)M_TOTAL * K_TOTAL];
__device__ __half g_wq[(size_t)N_TOTAL * K_TOTAL];

// ============================================================================
// Kernel 1: ternary-quantize W rows -> fp16 {-1,0,1}; thresh = 0.7*mean(|row|)
// ============================================================================
__global__ void __launch_bounds__(256) quant_w_kernel(const float* __restrict__ w,
                                                      uint2* __restrict__ wq) {
    const int row = blockIdx.x;
    const float4* wr = reinterpret_cast<const float4*>(w + (size_t)row * K_TOTAL);
    float s = 0.f;
#pragma unroll
    for (int i = 0; i < 4; ++i) {
        float4 v = wr[threadIdx.x + i * 256];
        s += fabsf(v.x) + fabsf(v.y) + fabsf(v.z) + fabsf(v.w);
    }
#pragma unroll
    for (int o = 16; o; o >>= 1) s += __shfl_xor_sync(0xffffffffu, s, o);
    __shared__ float warp_sums[8];
    if ((threadIdx.x & 31) == 0) warp_sums[threadIdx.x >> 5] = s;
    __syncthreads();
    float tot = 0.f;
#pragma unroll
    for (int i = 0; i < 8; ++i) tot += warp_sums[i];
    const float t = 0.7f * (tot * (1.0f / (float)K_TOTAL));

    uint2* wo = wq + (size_t)row * (K_TOTAL / 4);
#pragma unroll
    for (int i = 0; i < 4; ++i) {
        const int idx = threadIdx.x + i * 256;
        float4 v = wr[idx];
        float q0 = v.x > t ? 1.f : (v.x < -t ? -1.f : 0.f);
        float q1 = v.y > t ? 1.f : (v.y < -t ? -1.f : 0.f);
        float q2 = v.z > t ? 1.f : (v.z < -t ? -1.f : 0.f);
        float q3 = v.w > t ? 1.f : (v.w < -t ? -1.f : 0.f);
        __half2 p0 = __floats2half2_rn(q0, q1);
        __half2 p1 = __floats2half2_rn(q2, q3);
        uint2 u;
        u.x = *reinterpret_cast<uint32_t*>(&p0);
        u.y = *reinterpret_cast<uint32_t*>(&p1);
        wo[idx] = u;
    }
}

// ============================================================================
// Kernel 2: convert x (fp32) -> fp16
// ============================================================================
__global__ void __launch_bounds__(256) conv_x_kernel(const float4* __restrict__ x4,
                                                     uint2* __restrict__ xh) {
    const int i = blockIdx.x * 256 + threadIdx.x;
    float4 v = x4[i];
    __half2 p0 = __floats2half2_rn(v.x, v.y);
    __half2 p1 = __floats2half2_rn(v.z, v.w);
    uint2 u;
    u.x = *reinterpret_cast<uint32_t*>(&p0);
    u.y = *reinterpret_cast<uint32_t*>(&p1);
    xh[i] = u;
}

// ============================================================================
// GEMM: 128x256 CTA tile, BK=64, 4-stage cp.async pipeline, 8 warps (2x4),
// warp tile 64x64, mma.sync m16n8k16 fp16 -> fp32 accum.
// ============================================================================
constexpr int BM = 128, BN = 256, BK = 64, STAGES = 4;
constexpr int K_ITERS = K_TOTAL / BK;               // 64
constexpr int A_BYTES = BM * BK * 2;                // 16384
constexpr int B_BYTES = BN * BK * 2;                // 32768
constexpr int STAGE_BYTES = A_BYTES + B_BYTES;      // 49152
constexpr int SMEM_BYTES = STAGES * STAGE_BYTES;    // 196608

__device__ __forceinline__ void cp16(uint32_t s, const void* g) {
    asm volatile("cp.async.cg.shared.global [%0], [%1], 16;" :: "r"(s), "l"(g));
}
__device__ __forceinline__ void ldsm4(uint32_t* d, uint32_t a) {
    asm volatile("ldmatrix.sync.aligned.m8n8.x4.shared.b16 {%0,%1,%2,%3}, [%4];"
                 : "=r"(d[0]), "=r"(d[1]), "=r"(d[2]), "=r"(d[3]) : "r"(a));
}
__device__ __forceinline__ void mma16816(float* c, const uint32_t* a,
                                         uint32_t b0, uint32_t b1) {
    asm volatile(
        "mma.sync.aligned.m16n8k16.row.col.f32.f16.f16.f32 "
        "{%0,%1,%2,%3}, {%4,%5,%6,%7}, {%8,%9}, {%0,%1,%2,%3};"
        : "+f"(c[0]), "+f"(c[1]), "+f"(c[2]), "+f"(c[3])
        : "r"(a[0]), "r"(a[1]), "r"(a[2]), "r"(a[3]), "r"(b0), "r"(b1));
}

__global__ void __launch_bounds__(256, 1) ternary_gemm_kernel(
    const __half* __restrict__ xh,
    const __half* __restrict__ wq,
    const float* __restrict__ bias,
    float* __restrict__ out)
{
    extern __shared__ __align__(1024) char smem[];
    const uint32_t sb = (uint32_t)__cvta_generic_to_shared(smem);
    const int tid = threadIdx.x;
    const int wid = tid >> 5;
    const int lid = tid & 31;
    const int warp_m = wid & 1;       // 0..1 -> 64-row slab
    const int warp_n = wid >> 1;      // 0..3 -> 64-col slab
    const int m0 = blockIdx.y * BM;
    const int n0 = blockIdx.x * BN;

    // ---- stage loader: 16B chunks, XOR-8 swizzle on 128B rows ----
    auto load_stage = [&](int slot, int k0) {
        const uint32_t base = sb + slot * STAGE_BYTES;
#pragma unroll
        for (int i = 0; i < 4; ++i) {           // A: 128x64 halves = 1024 chunks
            int c = tid + i * 256, row = c >> 3, ch = c & 7;
            cp16(base + row * 128 + ((ch ^ (row & 7)) << 4),
                 xh + (size_t)(m0 + row) * K_TOTAL + k0 + ch * 8);
        }
#pragma unroll
        for (int i = 0; i < 8; ++i) {           // B: 256x64 halves = 2048 chunks
            int c = tid + i * 256, row = c >> 3, ch = c & 7;
            cp16(base + A_BYTES + row * 128 + ((ch ^ (row & 7)) << 4),
                 wq + (size_t)(n0 + row) * K_TOTAL + k0 + ch * 8);
        }
    };

    float acc[4][8][4];
#pragma unroll
    for (int i = 0; i < 4; ++i)
#pragma unroll
        for (int j = 0; j < 8; ++j)
#pragma unroll
            for (int r = 0; r < 4; ++r) acc[i][j][r] = 0.f;

    // ---- prologue: fill STAGES-1 stages ----
#pragma unroll
    for (int s = 0; s < STAGES - 1; ++s) {
        load_stage(s, s * BK);
        asm volatile("cp.async.commit_group;" ::: "memory");
    }

    // lane-constant address pieces (swizzle phase = lid&7)
    const uint32_t sw   = lid & 7;
    const uint32_t aoff = (warp_m * 64 + (lid & 15)) * 128;
    const uint32_t acb  = (uint32_t)(lid >> 4);
    const uint32_t boff = A_BYTES +
                          (warp_n * 64 + ((lid >> 4) << 3) + (lid & 7)) * 128;
    const uint32_t bcb  = (lid >> 3) & 1;

    for (int it = 0; it < K_ITERS; ++it) {
        asm volatile("cp.async.wait_group %0;" :: "n"(STAGES - 2) : "memory");
        __syncthreads();
        const int nx = it + STAGES - 1;
        if (nx < K_ITERS) load_stage(nx % STAGES, nx * BK);
        asm volatile("cp.async.commit_group;" ::: "memory");

        const uint32_t st = sb + (it % STAGES) * STAGE_BYTES;
#pragma unroll
        for (int k16 = 0; k16 < 4; ++k16) {
            uint32_t b[4][4];
#pragma unroll
            for (int p = 0; p < 4; ++p)      // 2 n-tiles per ldmatrix.x4
                ldsm4(b[p], st + boff + p * 2048 + (((bcb + 2 * k16) ^ sw) << 4));
            uint32_t a[4][4];
#pragma unroll
            for (int mt = 0; mt < 4; ++mt)   // A frags
                ldsm4(a[mt], st + aoff + mt * 2048 + (((acb + 2 * k16) ^ sw) << 4));
#pragma unroll
            for (int mt = 0; mt < 4; ++mt)
#pragma unroll
                for (int nt = 0; nt < 8; ++nt)
                    mma16816(acc[mt][nt], a[mt],
                             b[nt >> 1][(nt & 1) * 2], b[nt >> 1][(nt & 1) * 2 + 1]);
        }
    }

    // ---- epilogue: bias add + float2 stores ----
    const int g = lid >> 2, t = lid & 3;
#pragma unroll
    for (int mt = 0; mt < 4; ++mt) {
        const int row = m0 + warp_m * 64 + mt * 16 + g;
        float* o0 = out + (size_t)row * N_TOTAL;
        float* o1 = out + (size_t)(row + 8) * N_TOTAL;
#pragma unroll
        for (int nt = 0; nt < 8; ++nt) {
            const int col = n0 + warp_n * 64 + nt * 8 + 2 * t;
            const float2 bv = *reinterpret_cast<const float2*>(bias + col);
            float2 v0 = {acc[mt][nt][0] + bv.x, acc[mt][nt][1] + bv.y};
            float2 v1 = {acc[mt][nt][2] + bv.x, acc[mt][nt][3] + bv.y};
            *reinterpret_cast<float2*>(o0 + col) = v0;
            *reinterpret_cast<float2*>(o1 + col) = v1;
        }
    }
}

// ============================================================================
// Host launcher
// ============================================================================
extern "C" void kernel_launch(void* const* d_in, const int* in_sizes, int n_in,
                              void* d_out, int out_size) {
    const float* x    = (const float*)d_in[0];
    const float* w    = (const float*)d_in[1];
    const float* bias = (const float*)d_in[2];
    float* out        = (float*)d_out;

    void *xh, *wq;
    cudaGetSymbolAddress(&xh, g_xh);
    cudaGetSymbolAddress(&wq, g_wq);

    quant_w_kernel<<<N_TOTAL, 256>>>(w, (uint2*)wq);
    conv_x_kernel<<<(int)(((size_t)M_TOTAL * K_TOTAL) / (4 * 256)), 256>>>(
        (const float4*)x, (uint2*)xh);

    cudaFuncSetAttribute(ternary_gemm_kernel,
                         cudaFuncAttributeMaxDynamicSharedMemorySize, SMEM_BYTES);
    dim3 grid(N_TOTAL / BN, M_TOTAL / BM);
    ternary_gemm_kernel<<<grid, 256, SMEM_BYTES>>>(
        (const __half*)xh, (const __half*)wq, bias, out);
}

// round 4
// speedup vs baseline: 1.7973x; 1.0660x over previous
#include <cuda_runtime.h>
#include <cuda_fp16.h>
#include <cstdint>

// ============================================================================
// out[8192,4096] = x[8192,4096] @ ternary(W)^T[4096,4096] + bias
// cp.async + ldmatrix + mma.sync m16n8k16 fp16->fp32 (baseline sm_100 PTX).
// R4: register double-buffered fragments + compile-time stage indexing.
// ============================================================================
#define M_TOTAL 8192
#define N_TOTAL 4096
#define K_TOTAL 4096

__device__ __half g_xh[(size_t)M_TOTAL * K_TOTAL];
__device__ __half g_wq[(size_t)N_TOTAL * K_TOTAL];

// ============================================================================
// Kernel 1: ternary-quantize W rows -> fp16 {-1,0,1}; thresh = 0.7*mean(|row|)
// ============================================================================
__global__ void __launch_bounds__(256) quant_w_kernel(const float* __restrict__ w,
                                                      uint2* __restrict__ wq) {
    const int row = blockIdx.x;
    const float4* wr = reinterpret_cast<const float4*>(w + (size_t)row * K_TOTAL);
    float s = 0.f;
#pragma unroll
    for (int i = 0; i < 4; ++i) {
        float4 v = wr[threadIdx.x + i * 256];
        s += fabsf(v.x) + fabsf(v.y) + fabsf(v.z) + fabsf(v.w);
    }
#pragma unroll
    for (int o = 16; o; o >>= 1) s += __shfl_xor_sync(0xffffffffu, s, o);
    __shared__ float warp_sums[8];
    if ((threadIdx.x & 31) == 0) warp_sums[threadIdx.x >> 5] = s;
    __syncthreads();
    float tot = 0.f;
#pragma unroll
    for (int i = 0; i < 8; ++i) tot += warp_sums[i];
    const float t = 0.7f * (tot * (1.0f / (float)K_TOTAL));

    uint2* wo = wq + (size_t)row * (K_TOTAL / 4);
#pragma unroll
    for (int i = 0; i < 4; ++i) {
        const int idx = threadIdx.x + i * 256;
        float4 v = wr[idx];
        float q0 = v.x > t ? 1.f : (v.x < -t ? -1.f : 0.f);
        float q1 = v.y > t ? 1.f : (v.y < -t ? -1.f : 0.f);
        float q2 = v.z > t ? 1.f : (v.z < -t ? -1.f : 0.f);
        float q3 = v.w > t ? 1.f : (v.w < -t ? -1.f : 0.f);
        __half2 p0 = __floats2half2_rn(q0, q1);
        __half2 p1 = __floats2half2_rn(q2, q3);
        uint2 u;
        u.x = *reinterpret_cast<uint32_t*>(&p0);
        u.y = *reinterpret_cast<uint32_t*>(&p1);
        wo[idx] = u;
    }
}

// ============================================================================
// Kernel 2: convert x (fp32) -> fp16
// ============================================================================
__global__ void __launch_bounds__(256) conv_x_kernel(const float4* __restrict__ x4,
                                                     uint2* __restrict__ xh) {
    const int i = blockIdx.x * 256 + threadIdx.x;
    float4 v = x4[i];
    __half2 p0 = __floats2half2_rn(v.x, v.y);
    __half2 p1 = __floats2half2_rn(v.z, v.w);
    uint2 u;
    u.x = *reinterpret_cast<uint32_t*>(&p0);
    u.y = *reinterpret_cast<uint32_t*>(&p1);
    xh[i] = u;
}

// ============================================================================
// GEMM: 128x256 CTA tile, BK=64, 4-stage cp.async pipeline, 8 warps (2x4),
// warp tile 64x64, mma.sync m16n8k16 fp16 -> fp32 accum.
// Fragments double-buffered in registers across k16 steps.
// ============================================================================
constexpr int BM = 128, BN = 256, BK = 64, STAGES = 4;
constexpr int K_ITERS = K_TOTAL / BK;               // 64
constexpr int A_BYTES = BM * BK * 2;                // 16384
constexpr int B_BYTES = BN * BK * 2;                // 32768
constexpr int STAGE_BYTES = A_BYTES + B_BYTES;      // 49152
constexpr int SMEM_BYTES = STAGES * STAGE_BYTES;    // 196608

__device__ __forceinline__ void cp16(uint32_t s, const void* g) {
    asm volatile("cp.async.cg.shared.global [%0], [%1], 16;" :: "r"(s), "l"(g));
}
__device__ __forceinline__ void ldsm4(uint32_t* d, uint32_t a) {
    asm volatile("ldmatrix.sync.aligned.m8n8.x4.shared.b16 {%0,%1,%2,%3}, [%4];"
                 : "=r"(d[0]), "=r"(d[1]), "=r"(d[2]), "=r"(d[3]) : "r"(a));
}
__device__ __forceinline__ void mma16816(float* c, const uint32_t* a,
                                         uint32_t b0, uint32_t b1) {
    asm volatile(
        "mma.sync.aligned.m16n8k16.row.col.f32.f16.f16.f32 "
        "{%0,%1,%2,%3}, {%4,%5,%6,%7}, {%8,%9}, {%0,%1,%2,%3};"
        : "+f"(c[0]), "+f"(c[1]), "+f"(c[2]), "+f"(c[3])
        : "r"(a[0]), "r"(a[1]), "r"(a[2]), "r"(a[3]), "r"(b0), "r"(b1));
}

__global__ void __launch_bounds__(256, 1) ternary_gemm_kernel(
    const __half* __restrict__ xh,
    const __half* __restrict__ wq,
    const float* __restrict__ bias,
    float* __restrict__ out)
{
    extern __shared__ __align__(1024) char smem[];
    const uint32_t sb = (uint32_t)__cvta_generic_to_shared(smem);
    const int tid = threadIdx.x;
    const int wid = tid >> 5;
    const int lid = tid & 31;
    const int warp_m = wid & 1;
    const int warp_n = wid >> 1;
    const int m0 = blockIdx.y * BM;
    const int n0 = blockIdx.x * BN;

    auto load_stage = [&](int slot, int k0) {
        const uint32_t base = sb + slot * STAGE_BYTES;
#pragma unroll
        for (int i = 0; i < 4; ++i) {           // A: 1024 x 16B chunks
            int c = tid + i * 256, row = c >> 3, ch = c & 7;
            cp16(base + row * 128 + ((ch ^ (row & 7)) << 4),
                 xh + (size_t)(m0 + row) * K_TOTAL + k0 + ch * 8);
        }
#pragma unroll
        for (int i = 0; i < 8; ++i) {           // B: 2048 x 16B chunks
            int c = tid + i * 256, row = c >> 3, ch = c & 7;
            cp16(base + A_BYTES + row * 128 + ((ch ^ (row & 7)) << 4),
                 wq + (size_t)(n0 + row) * K_TOTAL + k0 + ch * 8);
        }
    };

    float acc[4][8][4];
#pragma unroll
    for (int i = 0; i < 4; ++i)
#pragma unroll
        for (int j = 0; j < 8; ++j)
#pragma unroll
            for (int r = 0; r < 4; ++r) acc[i][j][r] = 0.f;

#pragma unroll
    for (int s = 0; s < STAGES - 1; ++s) {
        load_stage(s, s * BK);
        asm volatile("cp.async.commit_group;" ::: "memory");
    }

    // lane-constant address pieces (swizzle phase = lid&7)
    const uint32_t sw   = lid & 7;
    const uint32_t aoff = (warp_m * 64 + (lid & 15)) * 128;
    const uint32_t acb  = (uint32_t)(lid >> 4);
    const uint32_t boff = A_BYTES +
                          (warp_n * 64 + ((lid >> 4) << 3) + (lid & 7)) * 128;
    const uint32_t bcb  = (lid >> 3) & 1;

    uint32_t afr[2][4][4], bfr[2][4][4];

    // frag loaders: buffer bi, k16 step within stage st
    auto ld_frags = [&](uint32_t st, int bi, int k16) {
#pragma unroll
        for (int p = 0; p < 4; ++p)
            ldsm4(bfr[bi][p], st + boff + p * 2048 + (((bcb + 2 * k16) ^ sw) << 4));
#pragma unroll
        for (int mt = 0; mt < 4; ++mt)
            ldsm4(afr[bi][mt], st + aoff + mt * 2048 + (((acb + 2 * k16) ^ sw) << 4));
    };
    auto do_mma = [&](int bi) {
#pragma unroll
        for (int mt = 0; mt < 4; ++mt)
#pragma unroll
            for (int nt = 0; nt < 8; ++nt)
                mma16816(acc[mt][nt], afr[bi][mt],
                         bfr[bi][nt >> 1][(nt & 1) * 2],
                         bfr[bi][nt >> 1][(nt & 1) * 2 + 1]);
    };

    // outer loop unrolled by STAGES so stage indices are compile-time
    for (int ito = 0; ito < K_ITERS; ito += STAGES) {
#pragma unroll
        for (int s = 0; s < STAGES; ++s) {
            const int it = ito + s;
            asm volatile("cp.async.wait_group %0;" :: "n"(STAGES - 2) : "memory");
            __syncthreads();
            const int nx = it + STAGES - 1;
            if (nx < K_ITERS) load_stage(nx & (STAGES - 1), nx * BK);
            asm volatile("cp.async.commit_group;" ::: "memory");

            const uint32_t st = sb + s * STAGE_BYTES;
            ld_frags(st, 0, 0);
#pragma unroll
            for (int k16 = 0; k16 < 4; ++k16) {
                if (k16 < 3) ld_frags(st, (k16 + 1) & 1, k16 + 1);
                do_mma(k16 & 1);
            }
        }
    }

    // ---- epilogue: bias add + float2 stores ----
    const int g = lid >> 2, t = lid & 3;
#pragma unroll
    for (int mt = 0; mt < 4; ++mt) {
        const int row = m0 + warp_m * 64 + mt * 16 + g;
        float* o0 = out + (size_t)row * N_TOTAL;
        float* o1 = out + (size_t)(row + 8) * N_TOTAL;
#pragma unroll
        for (int nt = 0; nt < 8; ++nt) {
            const int col = n0 + warp_n * 64 + nt * 8 + 2 * t;
            const float2 bv = *reinterpret_cast<const float2*>(bias + col);
            float2 v0 = {acc[mt][nt][0] + bv.x, acc[mt][nt][1] + bv.y};
            float2 v1 = {acc[mt][nt][2] + bv.x, acc[mt][nt][3] + bv.y};
            *reinterpret_cast<float2*>(o0 + col) = v0;
            *reinterpret_cast<float2*>(o1 + col) = v1;
        }
    }
}

// ============================================================================
// Host launcher
// ============================================================================
extern "C" void kernel_launch(void* const* d_in, const int* in_sizes, int n_in,
                              void* d_out, int out_size) {
    const float* x    = (const float*)d_in[0];
    const float* w    = (const float*)d_in[1];
    const float* bias = (const float*)d_in[2];
    float* out        = (float*)d_out;

    void *xh, *wq;
    cudaGetSymbolAddress(&xh, g_xh);
    cudaGetSymbolAddress(&wq, g_wq);

    quant_w_kernel<<<N_TOTAL, 256>>>(w, (uint2*)wq);
    conv_x_kernel<<<(int)(((size_t)M_TOTAL * K_TOTAL) / (4 * 256)), 256>>>(
        (const float4*)x, (uint2*)xh);

    cudaFuncSetAttribute(ternary_gemm_kernel,
                         cudaFuncAttributeMaxDynamicSharedMemorySize, SMEM_BYTES);
    dim3 grid(N_TOTAL / BN, M_TOTAL / BM);
    ternary_gemm_kernel<<<grid, 256, SMEM_BYTES>>>(
        (const __half*)xh, (const __half*)wq, bias, out);
}

// round 5
// speedup vs baseline: 2.0214x; 1.1247x over previous
#include <cuda_runtime.h>
#include <cuda_fp16.h>
#include <cstdint>

// ============================================================================
// out[8192,4096] = x[8192,4096] @ ternary(W)^T[4096,4096] + bias
// cp.async + ldmatrix + mma.sync m16n8k16 fp16->fp32 (baseline sm_100 PTX).
// R5: CUTLASS-style cross-stage fragment prefetch — the wait_group/syncthreads
// and next-stage k16=0 frag loads are overlapped with the last MMA batch.
// ============================================================================
#define M_TOTAL 8192
#define N_TOTAL 4096
#define K_TOTAL 4096

__device__ __half g_xh[(size_t)M_TOTAL * K_TOTAL];
__device__ __half g_wq[(size_t)N_TOTAL * K_TOTAL];

// ============================================================================
// Kernel 1: ternary-quantize W rows -> fp16 {-1,0,1}; thresh = 0.7*mean(|row|)
// ============================================================================
__global__ void __launch_bounds__(256) quant_w_kernel(const float* __restrict__ w,
                                                      uint2* __restrict__ wq) {
    const int row = blockIdx.x;
    const float4* wr = reinterpret_cast<const float4*>(w + (size_t)row * K_TOTAL);
    float s = 0.f;
#pragma unroll
    for (int i = 0; i < 4; ++i) {
        float4 v = wr[threadIdx.x + i * 256];
        s += fabsf(v.x) + fabsf(v.y) + fabsf(v.z) + fabsf(v.w);
    }
#pragma unroll
    for (int o = 16; o; o >>= 1) s += __shfl_xor_sync(0xffffffffu, s, o);
    __shared__ float warp_sums[8];
    if ((threadIdx.x & 31) == 0) warp_sums[threadIdx.x >> 5] = s;
    __syncthreads();
    float tot = 0.f;
#pragma unroll
    for (int i = 0; i < 8; ++i) tot += warp_sums[i];
    const float t = 0.7f * (tot * (1.0f / (float)K_TOTAL));

    uint2* wo = wq + (size_t)row * (K_TOTAL / 4);
#pragma unroll
    for (int i = 0; i < 4; ++i) {
        const int idx = threadIdx.x + i * 256;
        float4 v = wr[idx];
        float q0 = v.x > t ? 1.f : (v.x < -t ? -1.f : 0.f);
        float q1 = v.y > t ? 1.f : (v.y < -t ? -1.f : 0.f);
        float q2 = v.z > t ? 1.f : (v.z < -t ? -1.f : 0.f);
        float q3 = v.w > t ? 1.f : (v.w < -t ? -1.f : 0.f);
        __half2 p0 = __floats2half2_rn(q0, q1);
        __half2 p1 = __floats2half2_rn(q2, q3);
        uint2 u;
        u.x = *reinterpret_cast<uint32_t*>(&p0);
        u.y = *reinterpret_cast<uint32_t*>(&p1);
        wo[idx] = u;
    }
}

// ============================================================================
// Kernel 2: convert x (fp32) -> fp16
// ============================================================================
__global__ void __launch_bounds__(256) conv_x_kernel(const float4* __restrict__ x4,
                                                     uint2* __restrict__ xh) {
    const int i = blockIdx.x * 256 + threadIdx.x;
    float4 v = x4[i];
    __half2 p0 = __floats2half2_rn(v.x, v.y);
    __half2 p1 = __floats2half2_rn(v.z, v.w);
    uint2 u;
    u.x = *reinterpret_cast<uint32_t*>(&p0);
    u.y = *reinterpret_cast<uint32_t*>(&p1);
    xh[i] = u;
}

// ============================================================================
// GEMM: 128x256 CTA tile, BK=64, 4-stage cp.async pipeline, 8 warps (2x4),
// warp tile 64x64, mma.sync m16n8k16 fp16 -> fp32 accum.
// ============================================================================
constexpr int BM = 128, BN = 256, BK = 64, STAGES = 4;
constexpr int K_ITERS = K_TOTAL / BK;               // 64
constexpr int A_BYTES = BM * BK * 2;                // 16384
constexpr int B_BYTES = BN * BK * 2;                // 32768
constexpr int STAGE_BYTES = A_BYTES + B_BYTES;      // 49152
constexpr int SMEM_BYTES = STAGES * STAGE_BYTES;    // 196608

__device__ __forceinline__ void cp16(uint32_t s, const void* g) {
    asm volatile("cp.async.cg.shared.global [%0], [%1], 16;" :: "r"(s), "l"(g));
}
__device__ __forceinline__ void ldsm4(uint32_t* d, uint32_t a) {
    asm volatile("ldmatrix.sync.aligned.m8n8.x4.shared.b16 {%0,%1,%2,%3}, [%4];"
                 : "=r"(d[0]), "=r"(d[1]), "=r"(d[2]), "=r"(d[3]) : "r"(a));
}
__device__ __forceinline__ void mma16816(float* c, const uint32_t* a,
                                         uint32_t b0, uint32_t b1) {
    asm volatile(
        "mma.sync.aligned.m16n8k16.row.col.f32.f16.f16.f32 "
        "{%0,%1,%2,%3}, {%4,%5,%6,%7}, {%8,%9}, {%0,%1,%2,%3};"
        : "+f"(c[0]), "+f"(c[1]), "+f"(c[2]), "+f"(c[3])
        : "r"(a[0]), "r"(a[1]), "r"(a[2]), "r"(a[3]), "r"(b0), "r"(b1));
}

__global__ void __launch_bounds__(256, 1) ternary_gemm_kernel(
    const __half* __restrict__ xh,
    const __half* __restrict__ wq,
    const float* __restrict__ bias,
    float* __restrict__ out)
{
    extern __shared__ __align__(1024) char smem[];
    const uint32_t sb = (uint32_t)__cvta_generic_to_shared(smem);
    const int tid = threadIdx.x;
    const int wid = tid >> 5;
    const int lid = tid & 31;
    const int warp_m = wid & 1;
    const int warp_n = wid >> 1;
    const int m0 = blockIdx.y * BM;
    const int n0 = blockIdx.x * BN;

    auto load_stage = [&](int slot, int k0) {
        const uint32_t base = sb + slot * STAGE_BYTES;
#pragma unroll
        for (int i = 0; i < 4; ++i) {           // A: 1024 x 16B chunks
            int c = tid + i * 256, row = c >> 3, ch = c & 7;
            cp16(base + row * 128 + ((ch ^ (row & 7)) << 4),
                 xh + (size_t)(m0 + row) * K_TOTAL + k0 + ch * 8);
        }
#pragma unroll
        for (int i = 0; i < 8; ++i) {           // B: 2048 x 16B chunks
            int c = tid + i * 256, row = c >> 3, ch = c & 7;
            cp16(base + A_BYTES + row * 128 + ((ch ^ (row & 7)) << 4),
                 wq + (size_t)(n0 + row) * K_TOTAL + k0 + ch * 8);
        }
    };

    float acc[4][8][4];
#pragma unroll
    for (int i = 0; i < 4; ++i)
#pragma unroll
        for (int j = 0; j < 8; ++j)
#pragma unroll
            for (int r = 0; r < 4; ++r) acc[i][j][r] = 0.f;

    // lane-constant address pieces (swizzle phase = lid&7)
    const uint32_t sw   = lid & 7;
    const uint32_t aoff = (warp_m * 64 + (lid & 15)) * 128;
    const uint32_t acb  = (uint32_t)(lid >> 4);
    const uint32_t boff = A_BYTES +
                          (warp_n * 64 + ((lid >> 4) << 3) + (lid & 7)) * 128;
    const uint32_t bcb  = (lid >> 3) & 1;

    uint32_t afr[2][4][4], bfr[2][4][4];

    auto ld_frags = [&](uint32_t st, int bi, int k16) {
#pragma unroll
        for (int p = 0; p < 4; ++p)
            ldsm4(bfr[bi][p], st + boff + p * 2048 + (((bcb + 2 * k16) ^ sw) << 4));
#pragma unroll
        for (int mt = 0; mt < 4; ++mt)
            ldsm4(afr[bi][mt], st + aoff + mt * 2048 + (((acb + 2 * k16) ^ sw) << 4));
    };
    auto do_mma = [&](int bi) {
#pragma unroll
        for (int mt = 0; mt < 4; ++mt)
#pragma unroll
            for (int nt = 0; nt < 8; ++nt)
                mma16816(acc[mt][nt], afr[bi][mt],
                         bfr[bi][nt >> 1][(nt & 1) * 2],
                         bfr[bi][nt >> 1][(nt & 1) * 2 + 1]);
    };

    // ---- prologue: fill STAGES-1 stages, wait for stage 0, preload frags ----
#pragma unroll
    for (int s = 0; s < STAGES - 1; ++s) {
        load_stage(s, s * BK);
        asm volatile("cp.async.commit_group;" ::: "memory");
    }
    asm volatile("cp.async.wait_group %0;" :: "n"(STAGES - 2) : "memory");
    __syncthreads();
    ld_frags(sb, 0, 0);

    // ---- mainloop: wait/sync + next-stage frag prefetch hidden under MMAs ----
    for (int it = 0; it < K_ITERS; ++it) {
        const uint32_t st  = sb + (it & (STAGES - 1)) * STAGE_BYTES;
        const uint32_t stn = sb + ((it + 1) & (STAGES - 1)) * STAGE_BYTES;
#pragma unroll
        for (int k16 = 0; k16 < 4; ++k16) {
            const int cur = k16 & 1, nxt = cur ^ 1;
            if (k16 == 3) {
                // stage boundary: wait for next stage data, barrier, then
                // prefetch its first frags while this batch's MMAs drain
                asm volatile("cp.async.wait_group %0;" :: "n"(STAGES - 2) : "memory");
                __syncthreads();
                if (it + 1 < K_ITERS) ld_frags(stn, nxt, 0);
            } else {
                ld_frags(st, nxt, k16 + 1);
            }
            if (k16 == 0) {
                const int nx = it + STAGES - 1;
                if (nx < K_ITERS) load_stage(nx & (STAGES - 1), nx * BK);
                asm volatile("cp.async.commit_group;" ::: "memory");
            }
            do_mma(cur);
        }
    }

    // ---- epilogue: bias add + float2 stores ----
    const int g = lid >> 2, t = lid & 3;
#pragma unroll
    for (int mt = 0; mt < 4; ++mt) {
        const int row = m0 + warp_m * 64 + mt * 16 + g;
        float* o0 = out + (size_t)row * N_TOTAL;
        float* o1 = out + (size_t)(row + 8) * N_TOTAL;
#pragma unroll
        for (int nt = 0; nt < 8; ++nt) {
            const int col = n0 + warp_n * 64 + nt * 8 + 2 * t;
            const float2 bv = *reinterpret_cast<const float2*>(bias + col);
            float2 v0 = {acc[mt][nt][0] + bv.x, acc[mt][nt][1] + bv.y};
            float2 v1 = {acc[mt][nt][2] + bv.x, acc[mt][nt][3] + bv.y};
            *reinterpret_cast<float2*>(o0 + col) = v0;
            *reinterpret_cast<float2*>(o1 + col) = v1;
        }
    }
}

// ============================================================================
// Host launcher
// ============================================================================
extern "C" void kernel_launch(void* const* d_in, const int* in_sizes, int n_in,
                              void* d_out, int out_size) {
    const float* x    = (const float*)d_in[0];
    const float* w    = (const float*)d_in[1];
    const float* bias = (const float*)d_in[2];
    float* out        = (float*)d_out;

    void *xh, *wq;
    cudaGetSymbolAddress(&xh, g_xh);
    cudaGetSymbolAddress(&wq, g_wq);

    quant_w_kernel<<<N_TOTAL, 256>>>(w, (uint2*)wq);
    conv_x_kernel<<<(int)(((size_t)M_TOTAL * K_TOTAL) / (4 * 256)), 256>>>(
        (const float4*)x, (uint2*)xh);

    cudaFuncSetAttribute(ternary_gemm_kernel,
                         cudaFuncAttributeMaxDynamicSharedMemorySize, SMEM_BYTES);
    dim3 grid(N_TOTAL / BN, M_TOTAL / BM);
    ternary_gemm_kernel<<<grid, 256, SMEM_BYTES>>>(
        (const __half*)xh, (const __half*)wq, bias, out);
}

// round 6
// speedup vs baseline: 2.0952x; 1.0365x over previous
#include <cuda_runtime.h>
#include <cuda_fp16.h>
#include <cstdint>

// ============================================================================
// out[8192,4096] = x[8192,4096] @ ternary(W)^T[4096,4096] + bias
// cp.async + ldmatrix + mma.sync m16n8k16 fp16->fp32 (baseline sm_100 PTX).
// R6: BK=128 / 2-stage pipeline (half the barriers), fused prep kernel.
// ============================================================================
#define M_TOTAL 8192
#define N_TOTAL 4096
#define K_TOTAL 4096

__device__ __half g_xh[(size_t)M_TOTAL * K_TOTAL];
__device__ __half g_wq[(size_t)N_TOTAL * K_TOTAL];

// ============================================================================
// Fused prep: blocks [0, 4096) ternary-quantize W rows -> fp16 {-1,0,1};
//             blocks [4096, ...) convert x fp32 -> fp16.
// ============================================================================
__global__ void __launch_bounds__(256) prep_kernel(const float* __restrict__ w,
                                                   uint2* __restrict__ wq,
                                                   const float4* __restrict__ x4,
                                                   uint2* __restrict__ xh) {
    if (blockIdx.x < N_TOTAL) {
        const int row = blockIdx.x;
        const float4* wr = reinterpret_cast<const float4*>(w + (size_t)row * K_TOTAL);
        float s = 0.f;
#pragma unroll
        for (int i = 0; i < 4; ++i) {
            float4 v = wr[threadIdx.x + i * 256];
            s += fabsf(v.x) + fabsf(v.y) + fabsf(v.z) + fabsf(v.w);
        }
#pragma unroll
        for (int o = 16; o; o >>= 1) s += __shfl_xor_sync(0xffffffffu, s, o);
        __shared__ float warp_sums[8];
        if ((threadIdx.x & 31) == 0) warp_sums[threadIdx.x >> 5] = s;
        __syncthreads();
        float tot = 0.f;
#pragma unroll
        for (int i = 0; i < 8; ++i) tot += warp_sums[i];
        const float t = 0.7f * (tot * (1.0f / (float)K_TOTAL));

        uint2* wo = wq + (size_t)row * (K_TOTAL / 4);
#pragma unroll
        for (int i = 0; i < 4; ++i) {
            const int idx = threadIdx.x + i * 256;
            float4 v = wr[idx];
            float q0 = v.x > t ? 1.f : (v.x < -t ? -1.f : 0.f);
            float q1 = v.y > t ? 1.f : (v.y < -t ? -1.f : 0.f);
            float q2 = v.z > t ? 1.f : (v.z < -t ? -1.f : 0.f);
            float q3 = v.w > t ? 1.f : (v.w < -t ? -1.f : 0.f);
            __half2 p0 = __floats2half2_rn(q0, q1);
            __half2 p1 = __floats2half2_rn(q2, q3);
            uint2 u;
            u.x = *reinterpret_cast<uint32_t*>(&p0);
            u.y = *reinterpret_cast<uint32_t*>(&p1);
            wo[idx] = u;
        }
    } else {
        const int i = (blockIdx.x - N_TOTAL) * 256 + threadIdx.x;
        float4 v = x4[i];
        __half2 p0 = __floats2half2_rn(v.x, v.y);
        __half2 p1 = __floats2half2_rn(v.z, v.w);
        uint2 u;
        u.x = *reinterpret_cast<uint32_t*>(&p0);
        u.y = *reinterpret_cast<uint32_t*>(&p1);
        xh[i] = u;
    }
}

// ============================================================================
// GEMM: 128x256 CTA tile, BK=128 (two 64-k sub-blocks), 2-stage pipeline,
// 8 warps (2x4), warp tile 64x64, mma.sync m16n8k16 fp16 -> fp32 accum.
// ============================================================================
constexpr int BM = 128, BN = 256, BK = 128, STAGES = 2;
constexpr int K_ITERS = K_TOTAL / BK;               // 32
constexpr int A_SUB = BM * 64 * 2;                  // 16384 (one 64-k A sub-block)
constexpr int B_SUB = BN * 64 * 2;                  // 32768 (one 64-k B sub-block)
constexpr int B0_OFF = 2 * A_SUB;                   // B region offset in stage
constexpr int STAGE_BYTES = 2 * A_SUB + 2 * B_SUB;  // 98304
constexpr int SMEM_BYTES = STAGES * STAGE_BYTES;    // 196608

__device__ __forceinline__ void cp16(uint32_t s, const void* g) {
    asm volatile("cp.async.cg.shared.global [%0], [%1], 16;" :: "r"(s), "l"(g));
}
__device__ __forceinline__ void ldsm4(uint32_t* d, uint32_t a) {
    asm volatile("ldmatrix.sync.aligned.m8n8.x4.shared.b16 {%0,%1,%2,%3}, [%4];"
                 : "=r"(d[0]), "=r"(d[1]), "=r"(d[2]), "=r"(d[3]) : "r"(a));
}
__device__ __forceinline__ void mma16816(float* c, const uint32_t* a,
                                         uint32_t b0, uint32_t b1) {
    asm volatile(
        "mma.sync.aligned.m16n8k16.row.col.f32.f16.f16.f32 "
        "{%0,%1,%2,%3}, {%4,%5,%6,%7}, {%8,%9}, {%0,%1,%2,%3};"
        : "+f"(c[0]), "+f"(c[1]), "+f"(c[2]), "+f"(c[3])
        : "r"(a[0]), "r"(a[1]), "r"(a[2]), "r"(a[3]), "r"(b0), "r"(b1));
}

__global__ void __launch_bounds__(256, 1) ternary_gemm_kernel(
    const __half* __restrict__ xh,
    const __half* __restrict__ wq,
    const float* __restrict__ bias,
    float* __restrict__ out)
{
    extern __shared__ __align__(1024) char smem[];
    const uint32_t sb = (uint32_t)__cvta_generic_to_shared(smem);
    const int tid = threadIdx.x;
    const int wid = tid >> 5;
    const int lid = tid & 31;
    const int warp_m = wid & 1;
    const int warp_n = wid >> 1;
    const int m0 = blockIdx.y * BM;
    const int n0 = blockIdx.x * BN;

    // one 64-k sub-block loader (identical layout to the proven R5 stage)
    auto load_sub_a = [&](uint32_t base, int k0) {
#pragma unroll
        for (int i = 0; i < 4; ++i) {           // 1024 x 16B chunks
            int c = tid + i * 256, row = c >> 3, ch = c & 7;
            cp16(base + row * 128 + ((ch ^ (row & 7)) << 4),
                 xh + (size_t)(m0 + row) * K_TOTAL + k0 + ch * 8);
        }
    };
    auto load_sub_b = [&](uint32_t base, int k0) {
#pragma unroll
        for (int i = 0; i < 8; ++i) {           // 2048 x 16B chunks
            int c = tid + i * 256, row = c >> 3, ch = c & 7;
            cp16(base + row * 128 + ((ch ^ (row & 7)) << 4),
                 wq + (size_t)(n0 + row) * K_TOTAL + k0 + ch * 8);
        }
    };
    auto load_stage = [&](int slot, int k0) {
        const uint32_t base = sb + slot * STAGE_BYTES;
        load_sub_a(base, k0);
        load_sub_a(base + A_SUB, k0 + 64);
        load_sub_b(base + B0_OFF, k0);
        load_sub_b(base + B0_OFF + B_SUB, k0 + 64);
    };

    float acc[4][8][4];
#pragma unroll
    for (int i = 0; i < 4; ++i)
#pragma unroll
        for (int j = 0; j < 8; ++j)
#pragma unroll
            for (int r = 0; r < 4; ++r) acc[i][j][r] = 0.f;

    // lane-constant address pieces (swizzle phase = lid&7)
    const uint32_t sw   = lid & 7;
    const uint32_t aoff = (warp_m * 64 + (lid & 15)) * 128;
    const uint32_t acb  = (uint32_t)(lid >> 4);
    const uint32_t boff = (warp_n * 64 + ((lid >> 4) << 3) + (lid & 7)) * 128;
    const uint32_t bcb  = (lid >> 3) & 1;

    uint32_t afr[2][4][4], bfr[2][4][4];

    // frag load for sub-k step kk (0..3) within sub-block bases
    auto ld_frags = [&](uint32_t a_base, uint32_t b_base, int bi, int kk) {
#pragma unroll
        for (int p = 0; p < 4; ++p)
            ldsm4(bfr[bi][p], b_base + boff + p * 2048 + (((bcb + 2 * kk) ^ sw) << 4));
#pragma unroll
        for (int mt = 0; mt < 4; ++mt)
            ldsm4(afr[bi][mt], a_base + aoff + mt * 2048 + (((acb + 2 * kk) ^ sw) << 4));
    };
    auto do_mma = [&](int bi) {
#pragma unroll
        for (int mt = 0; mt < 4; ++mt)
#pragma unroll
            for (int nt = 0; nt < 8; ++nt)
                mma16816(acc[mt][nt], afr[bi][mt],
                         bfr[bi][nt >> 1][(nt & 1) * 2],
                         bfr[bi][nt >> 1][(nt & 1) * 2 + 1]);
    };

    // ---- prologue: load stage 0, wait, preload first frags ----
    load_stage(0, 0);
    asm volatile("cp.async.commit_group;" ::: "memory");
    asm volatile("cp.async.wait_group 0;" ::: "memory");
    __syncthreads();
    ld_frags(sb, sb + B0_OFF, 0, 0);

    // ---- mainloop: 32 iters of 8 k16 steps; barrier once per 128 k ----
    for (int it = 0; it < K_ITERS; ++it) {
        const uint32_t st  = sb + (it & 1) * STAGE_BYTES;
        const uint32_t stn = sb + ((it + 1) & 1) * STAGE_BYTES;
#pragma unroll
        for (int k16 = 0; k16 < 8; ++k16) {
            const int cur = k16 & 1, nxt = cur ^ 1;
            if (k16 == 7) {
                // stage boundary: next stage's loads (issued at k16==0) done,
                // barrier, then prefetch its first frags under this MMA batch
                asm volatile("cp.async.wait_group 0;" ::: "memory");
                __syncthreads();
                if (it + 1 < K_ITERS) ld_frags(stn, stn + B0_OFF, nxt, 0);
            } else {
                const int kn = k16 + 1, sub = kn >> 2, kk = kn & 3;
                ld_frags(st + sub * A_SUB, st + B0_OFF + sub * B_SUB, nxt, kk);
            }
            if (k16 == 0) {
                if (it + 1 < K_ITERS) load_stage((it + 1) & 1, (it + 1) * BK);
                asm volatile("cp.async.commit_group;" ::: "memory");
            }
            do_mma(cur);
        }
    }

    // ---- epilogue: bias add + float2 stores ----
    const int g = lid >> 2, t = lid & 3;
#pragma unroll
    for (int mt = 0; mt < 4; ++mt) {
        const int row = m0 + warp_m * 64 + mt * 16 + g;
        float* o0 = out + (size_t)row * N_TOTAL;
        float* o1 = out + (size_t)(row + 8) * N_TOTAL;
#pragma unroll
        for (int nt = 0; nt < 8; ++nt) {
            const int col = n0 + warp_n * 64 + nt * 8 + 2 * t;
            const float2 bv = *reinterpret_cast<const float2*>(bias + col);
            float2 v0 = {acc[mt][nt][0] + bv.x, acc[mt][nt][1] + bv.y};
            float2 v1 = {acc[mt][nt][2] + bv.x, acc[mt][nt][3] + bv.y};
            *reinterpret_cast<float2*>(o0 + col) = v0;
            *reinterpret_cast<float2*>(o1 + col) = v1;
        }
    }
}

// ============================================================================
// Host launcher
// ============================================================================
extern "C" void kernel_launch(void* const* d_in, const int* in_sizes, int n_in,
                              void* d_out, int out_size) {
    const float* x    = (const float*)d_in[0];
    const float* w    = (const float*)d_in[1];
    const float* bias = (const float*)d_in[2];
    float* out        = (float*)d_out;

    void *xh, *wq;
    cudaGetSymbolAddress(&xh, g_xh);
    cudaGetSymbolAddress(&wq, g_wq);

    const int conv_blocks = (int)(((size_t)M_TOTAL * K_TOTAL) / (4 * 256));
    prep_kernel<<<N_TOTAL + conv_blocks, 256>>>(w, (uint2*)wq,
                                                (const float4*)x, (uint2*)xh);

    cudaFuncSetAttribute(ternary_gemm_kernel,
                         cudaFuncAttributeMaxDynamicSharedMemorySize, SMEM_BYTES);
    dim3 grid(N_TOTAL / BN, M_TOTAL / BM);
    ternary_gemm_kernel<<<grid, 256, SMEM_BYTES>>>(
        (const __half*)xh, (const __half*)wq, bias, out);
}